// round 9
// baseline (speedup 1.0000x reference)
#include <cuda_runtime.h>

#define CK_B 64
#define CK_P 12
#define CK_Q 12
#define CK_N 1024
#define CK_D 64
#define CK_BN (CK_B*CK_N)   // 65536 rows

// Scratch: [t][b][n][d]. Xe written here, layer1 overwrites in place with seq1.
__device__ float g_buf[(size_t)CK_P * CK_BN * CK_D];
__device__ float g_se2[CK_N * CK_D];
__device__ float g_te2[CK_B * CK_P * CK_D];
// Folded weights: Weff[k][j] = W[k][j] + W[k+128][j]  (support == identity)
__device__ float g_Wg1[128 * 128];
__device__ float g_Wc1[128 * 64];
__device__ float g_Wg2[128 * 128];
__device__ float g_Wc2[128 * 64];

typedef unsigned long long ull_t;

__device__ __forceinline__ float sigm(float x) {
    return __fdividef(1.0f, 1.0f + __expf(-x));
}
__device__ __forceinline__ float tanh_f(float x) {
    return __fdividef(2.0f, 1.0f + __expf(-2.0f * x)) - 1.0f;
}

// ---- packed fp32x2 primitives (Blackwell FFMA2; exact fp32, 2 FMA / instr) ----
__device__ __forceinline__ void ffma2(ull_t& d, ull_t a, ull_t b) {
    asm("fma.rn.f32x2 %0, %1, %2, %0;" : "+l"(d) : "l"(a), "l"(b));
}
__device__ __forceinline__ ull_t pack2(float x, float y) {
    ull_t r; asm("mov.b64 %0, {%1, %2};" : "=l"(r) : "f"(x), "f"(y)); return r;
}
__device__ __forceinline__ float2 unpack2(ull_t v) {
    float2 r; asm("mov.b64 {%0, %1}, %2;" : "=f"(r.x), "=f"(r.y) : "l"(v)); return r;
}

// ---------------------------------------------------------------- weight fold
__global__ void fold_k(const float* __restrict__ Wg1, const float* __restrict__ Wc1,
                       const float* __restrict__ Wg2, const float* __restrict__ Wc2) {
    int i = blockIdx.x * 256 + threadIdx.x;
    if (i < 128 * 128) {
        g_Wg1[i] = Wg1[i] + Wg1[i + 128 * 128];
        g_Wg2[i] = Wg2[i] + Wg2[i + 128 * 128];
    }
    if (i < 128 * 64) {
        g_Wc1[i] = Wc1[i] + Wc1[i + 128 * 64];
        g_Wc2[i] = Wc2[i] + Wc2[i + 128 * 64];
    }
}

// ---------------------------------------------------------------- SE embedding
__global__ void se_k(const float* __restrict__ SE, const float* __restrict__ W1,
                     const float* __restrict__ b1, const float* __restrict__ W2,
                     const float* __restrict__ b2) {
    __shared__ float srow[64];
    __shared__ float h[64];
    int n = blockIdx.x, d = threadIdx.x;
    srow[d] = SE[n * 64 + d];
    __syncthreads();
    float a = b1[d];
#pragma unroll 16
    for (int k = 0; k < 64; k++) a = fmaf(srow[k], W1[k * 64 + d], a);
    h[d] = fmaxf(a, 0.f);
    __syncthreads();
    float o = b2[d];
#pragma unroll 16
    for (int k = 0; k < 64; k++) o = fmaf(h[k], W2[k * 64 + d], o);
    g_se2[n * 64 + d] = o;
}

// ---------------------------------------------------------------- TE embedding
__global__ void te_k(const int* __restrict__ TE, const float* __restrict__ W1,
                     const float* __restrict__ b1, const float* __restrict__ W2,
                     const float* __restrict__ b2) {
    __shared__ float h[64];
    int bp = blockIdx.x;          // b*12 + p
    int b = bp / 12, p = bp % 12, d = threadIdx.x;
    int dow = TE[(b * 24 + p) * 2 + 0];
    int tod = TE[(b * 24 + p) * 2 + 1];
    float a = W1[dow * 64 + d] + W1[(7 + tod) * 64 + d] + b1[d];
    h[d] = fmaxf(a, 0.f);
    __syncthreads();
    float o = b2[d];
#pragma unroll 16
    for (int k = 0; k < 64; k++) o = fmaf(h[k], W2[k * 64 + d], o);
    g_te2[bp * 64 + d] = o;
}

// ---------------------------------------------------------------- FC_X_in + STE
// 256 threads: thread = 4 positions x 16 cols. 4x less SMEM W2 traffic per
// output than 1x64, and each W2 load feeds 4 packed FMAs. FFMA2 inner loop.
__global__ void __launch_bounds__(256) xe_k(
        const float* __restrict__ X, const float* __restrict__ W1,
        const float* __restrict__ b1, const float* __restrict__ W2,
        const float* __restrict__ b2) {
    __shared__ float sW2[64 * 64];
    __shared__ float sw1[64], sb1[64], sb2[64];
    int tid = threadIdx.x;  // 256
    for (int i = tid; i < 4096; i += 256) sW2[i] = W2[i];
    if (tid < 64) { sw1[tid] = W1[tid]; sb1[tid] = b1[tid]; sb2[tid] = b2[tid]; }
    __syncthreads();

    int cg = tid & 3;        // col group: cols cg*16 .. cg*16+15
    int pt = tid >> 2;       // 0..63 position-group within block
    size_t pbase = (size_t)blockIdx.x * 256 + (size_t)pt * 4;  // 4 consecutive positions

    // gather the 4 scalar x values (positions in g_buf order: pos = t*BN + b*N + n)
    float xv[4];
    int tt[4], bb[4], nn[4];
#pragma unroll
    for (int pp = 0; pp < 4; pp++) {
        size_t pos = pbase + pp;
        int t = (int)(pos >> 16);            // / CK_BN
        int r = (int)(pos & 65535);
        int b = r >> 10, n = r & 1023;
        tt[pp] = t; bb[pp] = b; nn[pp] = n;
        xv[pp] = X[(b * CK_P + t) * CK_N + n];
    }

    ull_t acc[4][8];   // [pos][col-pair], cols cg*16 + 2jp, +1
    {
        const ull_t* b2p = (const ull_t*)(sb2 + cg * 16);
#pragma unroll
        for (int jp = 0; jp < 8; jp++) {
            ull_t bv = b2p[jp];
#pragma unroll
            for (int pp = 0; pp < 4; pp++) acc[pp][jp] = bv;
        }
    }

#pragma unroll 4
    for (int d = 0; d < 64; d++) {
        float w1v = sw1[d], b1v = sb1[d];
        ull_t hx[4];
#pragma unroll
        for (int pp = 0; pp < 4; pp++) {
            float hv = fmaxf(fmaf(xv[pp], w1v, b1v), 0.f);
            hx[pp] = pack2(hv, hv);
        }
        const ulonglong2* wp = (const ulonglong2*)(sW2 + d * 64 + cg * 16);
        ulonglong2 wa = wp[0], wb = wp[1], wc = wp[2], wd = wp[3];
#pragma unroll
        for (int pp = 0; pp < 4; pp++) {
            ffma2(acc[pp][0], hx[pp], wa.x); ffma2(acc[pp][1], hx[pp], wa.y);
            ffma2(acc[pp][2], hx[pp], wb.x); ffma2(acc[pp][3], hx[pp], wb.y);
            ffma2(acc[pp][4], hx[pp], wc.x); ffma2(acc[pp][5], hx[pp], wc.y);
            ffma2(acc[pp][6], hx[pp], wd.x); ffma2(acc[pp][7], hx[pp], wd.y);
        }
    }

#pragma unroll
    for (int pp = 0; pp < 4; pp++) {
        const float* se = g_se2 + nn[pp] * 64 + cg * 16;
        const float* te = g_te2 + (bb[pp] * CK_P + tt[pp]) * 64 + cg * 16;
        float* outp = g_buf + (pbase + pp) * 64 + cg * 16;
#pragma unroll
        for (int q = 0; q < 4; q++) {   // 4 float4 stores = 16 cols
            float2 v0 = unpack2(acc[pp][q * 2 + 0]);
            float2 v1 = unpack2(acc[pp][q * 2 + 1]);
            float4 v;
            v.x = v0.x + se[q * 4 + 0] + te[q * 4 + 0];
            v.y = v0.y + se[q * 4 + 1] + te[q * 4 + 1];
            v.z = v1.x + se[q * 4 + 2] + te[q * 4 + 2];
            v.w = v1.y + se[q * 4 + 3] + te[q * 4 + 3];
            *(float4*)(outp + q * 4) = v;
        }
    }
}

// ---------------------------------------------------------------- DCGRU layer
// Persistent per-tile scan: block owns 64 rows, runs all 12 time steps with
// weights + state resident in SMEM. Inner GEMMs use packed fp32x2 FMA
// (column-pair packing: W loads directly as 64-bit pairs, A broadcast packed).
template<int LAYER, bool FINAL>
__global__ void __launch_bounds__(512, 1) gru_k(
        const float* __restrict__ bg, const float* __restrict__ bc,
        const float* __restrict__ Wo1, const float* __restrict__ bo1,
        const float* __restrict__ Wo2, const float* __restrict__ bo2,
        float* __restrict__ out) {
    extern __shared__ float sm[];
    float* sWg  = sm;            // [128][128]
    float* sWc  = sWg + 16384;   // [128][64]
    float* sZt  = sWc + 8192;    // [128][64]  k-major: rows 0..63 = x_t, 64..127 = r*s
    float* sSt  = sZt + 8192;    // [64][64]   state, k-major
    float* sU   = sSt + 4096;    // [64][64]   update gate
    float* sbg  = sU + 4096;     // 128
    float* sbc  = sbg + 128;     // 64
    float* sWo1 = sbc + 64;      // [64][64]
    float* sWo2 = sWo1 + 4096;   // [64][12]
    float* sbo1 = sWo2 + 768;    // 64
    float* sbo2 = sbo1 + 64;     // 12

    const float* Wg = (LAYER == 0) ? g_Wg1 : g_Wg2;
    const float* Wc = (LAYER == 0) ? g_Wc1 : g_Wc2;

    int tid = threadIdx.x;  // 512
    for (int i = tid; i < 16384; i += 512) sWg[i] = Wg[i];
    for (int i = tid; i < 8192; i += 512)  sWc[i] = Wc[i];
    for (int i = tid; i < 4096; i += 512)  sSt[i] = 0.f;
    if (tid < 128) sbg[tid] = bg[tid];
    if (tid < 64)  sbc[tid] = bc[tid];
    if (FINAL) {
        for (int i = tid; i < 4096; i += 512) sWo1[i] = Wo1[i];
        for (int i = tid; i < 768; i += 512)  sWo2[i] = Wo2[i];
        if (tid < 64)  sbo1[tid] = bo1[tid];
        if (tid < 12)  sbo2[tid] = bo2[tid];
    }
    __syncthreads();

    int row0 = blockIdx.x * 64;
    int tr = tid >> 4;   // 0..31 -> rows tr*2, tr*2+1
    int tc = tid & 15;   // 0..15
    int r0 = tr * 2;

    for (int t = 0; t < CK_P; t++) {
        // load x_t transposed into sZt[k][row]
        const float* src = g_buf + ((size_t)t * CK_BN + row0) * 64;
        for (int it = tid; it < 1024; it += 512) {
            int rr = it >> 4;
            int d4 = (it & 15) * 4;
            float4 v = *(const float4*)(src + rr * 64 + d4);
            sZt[(d4 + 0) * 64 + rr] = v.x;
            sZt[(d4 + 1) * 64 + rr] = v.y;
            sZt[(d4 + 2) * 64 + rr] = v.z;
            sZt[(d4 + 3) * 64 + rr] = v.w;
        }
        __syncthreads();

        // gate GEMM: [64 rows x 128 cols], K = 128 ( = [x | s] ), fp32x2 packed
        ull_t accg[2][4];
        {
            const ull_t* bgp = (const ull_t*)(sbg + tc * 8);
#pragma unroll
            for (int jp = 0; jp < 4; jp++) { accg[0][jp] = bgp[jp]; accg[1][jp] = bgp[jp]; }
        }
        {
            const float* aX = sZt + r0;
            const float* bW = sWg + tc * 8;
#pragma unroll 8
            for (int k = 0; k < 64; k++) {
                float2 a = *(const float2*)(aX + k * 64);
                ull_t ax = pack2(a.x, a.x), ay = pack2(a.y, a.y);
                const ulonglong2* wp = (const ulonglong2*)(bW + k * 128);
                ulonglong2 w01 = wp[0], w23 = wp[1];
                ffma2(accg[0][0], ax, w01.x); ffma2(accg[0][1], ax, w01.y);
                ffma2(accg[0][2], ax, w23.x); ffma2(accg[0][3], ax, w23.y);
                ffma2(accg[1][0], ay, w01.x); ffma2(accg[1][1], ay, w01.y);
                ffma2(accg[1][2], ay, w23.x); ffma2(accg[1][3], ay, w23.y);
            }
            const float* aS = sSt + r0;
            const float* bW2 = sWg + 64 * 128 + tc * 8;
#pragma unroll 8
            for (int k = 0; k < 64; k++) {
                float2 a = *(const float2*)(aS + k * 64);
                ull_t ax = pack2(a.x, a.x), ay = pack2(a.y, a.y);
                const ulonglong2* wp = (const ulonglong2*)(bW2 + k * 128);
                ulonglong2 w01 = wp[0], w23 = wp[1];
                ffma2(accg[0][0], ax, w01.x); ffma2(accg[0][1], ax, w01.y);
                ffma2(accg[0][2], ax, w23.x); ffma2(accg[0][3], ax, w23.y);
                ffma2(accg[1][0], ay, w01.x); ffma2(accg[1][1], ay, w01.y);
                ffma2(accg[1][2], ay, w23.x); ffma2(accg[1][3], ay, w23.y);
            }
        }
        float vals[2][8];
#pragma unroll
        for (int i = 0; i < 2; i++)
#pragma unroll
            for (int jp = 0; jp < 4; jp++) {
                float2 v = unpack2(accg[i][jp]);
                vals[i][jp * 2 + 0] = v.x;
                vals[i][jp * 2 + 1] = v.y;
            }
        // sigmoid; cols 0..63 = r -> stage r*s into sZt bottom; cols 64..127 = u -> sU
        if (tc < 8) {
#pragma unroll
            for (int i = 0; i < 2; i++)
#pragma unroll
                for (int j = 0; j < 8; j++) {
                    int col = tc * 8 + j, row = r0 + i;
                    float rv = sigm(vals[i][j]);
                    sZt[(64 + col) * 64 + row] = rv * sSt[col * 64 + row];
                }
        } else {
#pragma unroll
            for (int i = 0; i < 2; i++)
#pragma unroll
                for (int j = 0; j < 8; j++) {
                    int col = tc * 8 + j - 64, row = r0 + i;
                    sU[col * 64 + row] = sigm(vals[i][j]);
                }
        }
        __syncthreads();

        // candidate GEMM: [64 x 64], K = 128 ( = [x | r*s] ), fp32x2 packed
        ull_t accc[2][2];
        {
            const ull_t* bcp = (const ull_t*)(sbc + tc * 4);
            accc[0][0] = bcp[0]; accc[0][1] = bcp[1];
            accc[1][0] = bcp[0]; accc[1][1] = bcp[1];
        }
        {
            const float* aZ = sZt + r0;
            const float* bC = sWc + tc * 4;
#pragma unroll 8
            for (int k = 0; k < 128; k++) {
                float2 a = *(const float2*)(aZ + k * 64);
                ull_t ax = pack2(a.x, a.x), ay = pack2(a.y, a.y);
                ulonglong2 w = *(const ulonglong2*)(bC + k * 64);
                ffma2(accc[0][0], ax, w.x); ffma2(accc[0][1], ax, w.y);
                ffma2(accc[1][0], ay, w.x); ffma2(accc[1][1], ay, w.y);
            }
        }
        // state update: new = c + u*(s - c)
#pragma unroll
        for (int i = 0; i < 2; i++) {
            int row = r0 + i;
            float2 c0 = unpack2(accc[i][0]);
            float2 c1 = unpack2(accc[i][1]);
            float cvv[4] = {c0.x, c0.y, c1.x, c1.y};
            float4 nv;
            float* nvp = &nv.x;
#pragma unroll
            for (int j = 0; j < 4; j++) {
                int col = tc * 4 + j;
                float cv = tanh_f(cvv[j]);
                float u = sU[col * 64 + row];
                float s = sSt[col * 64 + row];
                float v = fmaf(u, s - cv, cv);
                sSt[col * 64 + row] = v;
                nvp[j] = v;
            }
            if (!FINAL) {
                *(float4*)(g_buf + ((size_t)t * CK_BN + row0 + row) * 64 + tc * 4) = nv;
            }
        }
        __syncthreads();
    }

    if (FINAL) {
        // o1 = relu(h @ Wo1 + bo1): [64 x 64], K = 64, fp32x2 packed
        ull_t acco[2][2];
        {
            const ull_t* bop = (const ull_t*)(sbo1 + tc * 4);
            acco[0][0] = bop[0]; acco[0][1] = bop[1];
            acco[1][0] = bop[0]; acco[1][1] = bop[1];
        }
        {
            const float* aS = sSt + r0;
            const float* bC = sWo1 + tc * 4;
#pragma unroll 8
            for (int k = 0; k < 64; k++) {
                float2 a = *(const float2*)(aS + k * 64);
                ull_t ax = pack2(a.x, a.x), ay = pack2(a.y, a.y);
                ulonglong2 w = *(const ulonglong2*)(bC + k * 64);
                ffma2(acco[0][0], ax, w.x); ffma2(acco[0][1], ax, w.y);
                ffma2(acco[1][0], ay, w.x); ffma2(acco[1][1], ay, w.y);
            }
        }
#pragma unroll
        for (int i = 0; i < 2; i++) {
            float2 v0 = unpack2(acco[i][0]);
            float2 v1 = unpack2(acco[i][1]);
            float vv[4] = {v0.x, v0.y, v1.x, v1.y};
#pragma unroll
            for (int j = 0; j < 4; j++)
                sZt[(tc * 4 + j) * 64 + (r0 + i)] = fmaxf(vv[j], 0.f);
        }
        __syncthreads();

        // y = o1 @ Wo2 + bo2 -> out[b][q][n]
        for (int idx = tid; idx < 64 * 12; idx += 512) {
            int row = idx / 12, q = idx % 12;
            float a = sbo2[q];
#pragma unroll 16
            for (int k = 0; k < 64; k++) a = fmaf(sZt[k * 64 + row], sWo2[k * 12 + q], a);
            int rowg = row0 + row;
            int b = rowg >> 10, n = rowg & 1023;
            out[((size_t)b * CK_Q + q) * CK_N + n] = a;
        }
    }
}

// ---------------------------------------------------------------- launch
extern "C" void kernel_launch(void* const* d_in, const int* in_sizes, int n_in,
                              void* d_out, int out_size) {
    const float* X     = (const float*)d_in[0];
    const float* SE    = (const float*)d_in[3];
    const float* W_se1 = (const float*)d_in[4];
    const float* b_se1 = (const float*)d_in[5];
    const float* W_se2 = (const float*)d_in[6];
    const float* b_se2 = (const float*)d_in[7];
    const float* W_te1 = (const float*)d_in[8];
    const float* b_te1 = (const float*)d_in[9];
    const float* W_te2 = (const float*)d_in[10];
    const float* b_te2 = (const float*)d_in[11];
    const float* W_in1 = (const float*)d_in[12];
    const float* b_in1 = (const float*)d_in[13];
    const float* W_in2 = (const float*)d_in[14];
    const float* b_in2 = (const float*)d_in[15];
    const float* Wg1   = (const float*)d_in[16];
    const float* bg1   = (const float*)d_in[17];
    const float* Wc1   = (const float*)d_in[18];
    const float* bc1   = (const float*)d_in[19];
    const float* Wg2   = (const float*)d_in[20];
    const float* bg2   = (const float*)d_in[21];
    const float* Wc2   = (const float*)d_in[22];
    const float* bc2   = (const float*)d_in[23];
    const float* W_o1  = (const float*)d_in[24];
    const float* b_o1  = (const float*)d_in[25];
    const float* W_o2  = (const float*)d_in[26];
    const float* b_o2  = (const float*)d_in[27];
    const int*   TE    = (const int*)d_in[28];
    float* out = (float*)d_out;

    size_t smem = (size_t)(16384 + 8192 + 8192 + 4096 + 4096 + 128 + 64 +
                           4096 + 768 + 64 + 16) * sizeof(float);
    cudaFuncSetAttribute(gru_k<0, false>, cudaFuncAttributeMaxDynamicSharedMemorySize, (int)smem);
    cudaFuncSetAttribute(gru_k<1, true>,  cudaFuncAttributeMaxDynamicSharedMemorySize, (int)smem);

    fold_k<<<64, 256>>>(Wg1, Wc1, Wg2, Wc2);
    se_k<<<CK_N, 64>>>(SE, W_se1, b_se1, W_se2, b_se2);
    te_k<<<CK_B * CK_P, 64>>>(TE, W_te1, b_te1, W_te2, b_te2);
    xe_k<<<(CK_P * CK_BN) / 256, 256>>>(X, W_in1, b_in1, W_in2, b_in2);
    gru_k<0, false><<<CK_BN / 64, 512, smem>>>(bg1, bc1, nullptr, nullptr, nullptr, nullptr, nullptr);
    gru_k<1, true><<<CK_BN / 64, 512, smem>>>(bg2, bc2, W_o1, b_o1, W_o2, b_o2, out);
}

// round 12
// speedup vs baseline: 4.2419x; 4.2419x over previous
#include <cuda_runtime.h>
#include <cstdint>

#define CK_B 64
#define CK_P 12
#define CK_Q 12
#define CK_N 1024
#define CK_D 64
#define CK_BN (CK_B*CK_N)

__device__ float g_buf[(size_t)CK_P * CK_BN * CK_D];
__device__ float g_se2[CK_N * CK_D];
__device__ float g_te2[CK_B * CK_P * CK_D];
// Folded (support==I), transposed [n][k] with k-stride 132, tf32-rounded
__device__ float g_WgT1[128 * 132];
__device__ float g_WgT2[128 * 132];
__device__ float g_WcT1[64 * 132];
__device__ float g_WcT2[64 * 132];

typedef unsigned long long ull_t;

__device__ __forceinline__ float sigm(float x) {
    return __fdividef(1.0f, 1.0f + __expf(-x));
}
__device__ __forceinline__ float tanh_f(float x) {
    return __fdividef(2.0f, 1.0f + __expf(-2.0f * x)) - 1.0f;
}
__device__ __forceinline__ uint32_t tf32r(float x) {
    uint32_t r; asm("cvt.rna.tf32.f32 %0, %1;" : "=r"(r) : "f"(x)); return r;
}
// m16n8k8 tf32 mma, C += A*B
__device__ __forceinline__ void mma8(float* c, const uint32_t* a, const uint32_t* b) {
    asm volatile(
        "mma.sync.aligned.m16n8k8.row.col.f32.tf32.tf32.f32 "
        "{%0,%1,%2,%3}, {%4,%5,%6,%7}, {%8,%9}, {%0,%1,%2,%3};"
        : "+f"(c[0]), "+f"(c[1]), "+f"(c[2]), "+f"(c[3])
        : "r"(a[0]), "r"(a[1]), "r"(a[2]), "r"(a[3]), "r"(b[0]), "r"(b[1]));
}

// SMEM float-index layout (total 47376 floats = 189.5 KB)
#define WG_F   0
#define WC_F   16896
#define A_F    25344
#define BG_F   42240
#define BC_F   42368
#define WO1_F  42432
#define WO2_F  46528
#define BO1_F  47296
#define BO2_F  47360
#define SMEM_F 47376

// ---------------------------------------------------------------- weight prep
__global__ void fold3_k(const float* __restrict__ Wg1, const float* __restrict__ Wc1,
                        const float* __restrict__ Wg2, const float* __restrict__ Wc2) {
    int i = blockIdx.x * 256 + threadIdx.x;
    if (i < 128 * 132) {
        int n = i / 132, k = i - n * 132;
        float v1 = 0.f, v2 = 0.f;
        if (k < 128) {
            v1 = __uint_as_float(tf32r(Wg1[k * 128 + n] + Wg1[(k + 128) * 128 + n]));
            v2 = __uint_as_float(tf32r(Wg2[k * 128 + n] + Wg2[(k + 128) * 128 + n]));
        }
        g_WgT1[i] = v1; g_WgT2[i] = v2;
    }
    if (i < 64 * 132) {
        int n = i / 132, k = i - n * 132;
        float v1 = 0.f, v2 = 0.f;
        if (k < 128) {
            v1 = __uint_as_float(tf32r(Wc1[k * 64 + n] + Wc1[(k + 128) * 64 + n]));
            v2 = __uint_as_float(tf32r(Wc2[k * 64 + n] + Wc2[(k + 128) * 64 + n]));
        }
        g_WcT1[i] = v1; g_WcT2[i] = v2;
    }
}

// ---------------------------------------------------------------- SE embedding
__global__ void se_k(const float* __restrict__ SE, const float* __restrict__ W1,
                     const float* __restrict__ b1, const float* __restrict__ W2,
                     const float* __restrict__ b2) {
    __shared__ float srow[64];
    __shared__ float h[64];
    int n = blockIdx.x, d = threadIdx.x;
    srow[d] = SE[n * 64 + d];
    __syncthreads();
    float a = b1[d];
#pragma unroll 16
    for (int k = 0; k < 64; k++) a = fmaf(srow[k], W1[k * 64 + d], a);
    h[d] = fmaxf(a, 0.f);
    __syncthreads();
    float o = b2[d];
#pragma unroll 16
    for (int k = 0; k < 64; k++) o = fmaf(h[k], W2[k * 64 + d], o);
    g_se2[n * 64 + d] = o;
}

// ---------------------------------------------------------------- TE embedding
__global__ void te_k(const int* __restrict__ TE, const float* __restrict__ W1,
                     const float* __restrict__ b1, const float* __restrict__ W2,
                     const float* __restrict__ b2) {
    __shared__ float h[64];
    int bp = blockIdx.x;
    int b = bp / 12, p = bp % 12, d = threadIdx.x;
    int dow = TE[(b * 24 + p) * 2 + 0];
    int tod = TE[(b * 24 + p) * 2 + 1];
    float a = W1[dow * 64 + d] + W1[(7 + tod) * 64 + d] + b1[d];
    h[d] = fmaxf(a, 0.f);
    __syncthreads();
    float o = b2[d];
#pragma unroll 16
    for (int k = 0; k < 64; k++) o = fmaf(h[k], W2[k * 64 + d], o);
    g_te2[bp * 64 + d] = o;
}

// ---------------------------------------------------------------- FC_X_in + STE
__device__ __forceinline__ void ffma2(ull_t& d, ull_t a, ull_t b) {
    asm("fma.rn.f32x2 %0, %1, %2, %0;" : "+l"(d) : "l"(a), "l"(b));
}
__device__ __forceinline__ ull_t pack2(float x, float y) {
    ull_t r; asm("mov.b64 %0, {%1, %2};" : "=l"(r) : "f"(x), "f"(y)); return r;
}
__device__ __forceinline__ float2 unpack2(ull_t v) {
    float2 r; asm("mov.b64 {%0, %1}, %2;" : "=f"(r.x), "=f"(r.y) : "l"(v)); return r;
}

__global__ void __launch_bounds__(256) xe_k(
        const float* __restrict__ X, const float* __restrict__ W1,
        const float* __restrict__ b1, const float* __restrict__ W2,
        const float* __restrict__ b2) {
    __shared__ float sW2[64 * 64];
    __shared__ float sw1[64], sb1[64], sb2[64];
    int tid = threadIdx.x;
    for (int i = tid; i < 4096; i += 256) sW2[i] = W2[i];
    if (tid < 64) { sw1[tid] = W1[tid]; sb1[tid] = b1[tid]; sb2[tid] = b2[tid]; }
    __syncthreads();

    int cg = tid & 3;
    int pt = tid >> 2;
    size_t pbase = (size_t)blockIdx.x * 256 + (size_t)pt * 4;

    float xv[4];
    int tt[4], bb[4], nn[4];
#pragma unroll
    for (int pp = 0; pp < 4; pp++) {
        size_t pos = pbase + pp;
        int t = (int)(pos >> 16);
        int r = (int)(pos & 65535);
        int b = r >> 10, n = r & 1023;
        tt[pp] = t; bb[pp] = b; nn[pp] = n;
        xv[pp] = X[(b * CK_P + t) * CK_N + n];
    }
    ull_t acc[4][8];
    {
        const ull_t* b2p = (const ull_t*)(sb2 + cg * 16);
#pragma unroll
        for (int jp = 0; jp < 8; jp++) {
            ull_t bv = b2p[jp];
#pragma unroll
            for (int pp = 0; pp < 4; pp++) acc[pp][jp] = bv;
        }
    }
#pragma unroll 4
    for (int d = 0; d < 64; d++) {
        float w1v = sw1[d], b1v = sb1[d];
        ull_t hx[4];
#pragma unroll
        for (int pp = 0; pp < 4; pp++) {
            float hv = fmaxf(fmaf(xv[pp], w1v, b1v), 0.f);
            hx[pp] = pack2(hv, hv);
        }
        const ulonglong2* wp = (const ulonglong2*)(sW2 + d * 64 + cg * 16);
        ulonglong2 wa = wp[0], wb = wp[1], wc = wp[2], wd = wp[3];
#pragma unroll
        for (int pp = 0; pp < 4; pp++) {
            ffma2(acc[pp][0], hx[pp], wa.x); ffma2(acc[pp][1], hx[pp], wa.y);
            ffma2(acc[pp][2], hx[pp], wb.x); ffma2(acc[pp][3], hx[pp], wb.y);
            ffma2(acc[pp][4], hx[pp], wc.x); ffma2(acc[pp][5], hx[pp], wc.y);
            ffma2(acc[pp][6], hx[pp], wd.x); ffma2(acc[pp][7], hx[pp], wd.y);
        }
    }
#pragma unroll
    for (int pp = 0; pp < 4; pp++) {
        const float* se = g_se2 + nn[pp] * 64 + cg * 16;
        const float* te = g_te2 + (bb[pp] * CK_P + tt[pp]) * 64 + cg * 16;
        float* outp = g_buf + (pbase + pp) * 64 + cg * 16;
#pragma unroll
        for (int q = 0; q < 4; q++) {
            float2 v0 = unpack2(acc[pp][q * 2 + 0]);
            float2 v1 = unpack2(acc[pp][q * 2 + 1]);
            float4 v;
            v.x = v0.x + se[q * 4 + 0] + te[q * 4 + 0];
            v.y = v0.y + se[q * 4 + 1] + te[q * 4 + 1];
            v.z = v1.x + se[q * 4 + 2] + te[q * 4 + 2];
            v.w = v1.y + se[q * 4 + 3] + te[q * 4 + 3];
            *(float4*)(outp + q * 4) = v;
        }
    }
}

// ---------------------------------------------------------------- DCGRU (mma.sync tf32)
// Block = 128 rows x 12 steps. A[128][132] = [x | s] tf32 in SMEM.
// Gate GEMM 128x128: 16 warps, 32x32 tiles; warp w: rows (w&3)*32.., cols (w>>2)*32..
// Warps 8..15 own gate u-half == cand output == state (same lane->coord map),
// so u and s stay in registers; only r*s transits SMEM.
template<int LAYER, bool FINAL>
__global__ void __launch_bounds__(512, 1) gru3_k(
        const float* __restrict__ bg, const float* __restrict__ bc,
        const float* __restrict__ Wo1, const float* __restrict__ bo1,
        const float* __restrict__ Wo2, const float* __restrict__ bo2,
        float* __restrict__ out) {
    extern __shared__ float sm[];
    int tid = threadIdx.x, wid = tid >> 5, lane = tid & 31;
    int g4 = lane >> 2, t4 = lane & 3;
    int gr = wid & 3, gc = wid >> 2;
    int row0 = blockIdx.x * 128;

    {   // stage weights / biases
        const float* Wgs = (LAYER == 0) ? g_WgT1 : g_WgT2;
        for (int i = tid; i < 128 * 132; i += 512) sm[WG_F + i] = Wgs[i];
        const float* Wcs = (LAYER == 0) ? g_WcT1 : g_WcT2;
        for (int i = tid; i < 64 * 132; i += 512) sm[WC_F + i] = Wcs[i];
        if (tid < 128) sm[BG_F + tid] = bg[tid];
        if (tid < 64)  sm[BC_F + tid] = bc[tid];
        if (FINAL) {
            for (int i = tid; i < 4096; i += 512) sm[WO1_F + i] = Wo1[i];
            for (int i = tid; i < 768; i += 512)  sm[WO2_F + i] = Wo2[i];
            if (tid < 64) sm[BO1_F + tid] = bo1[tid];
            if (tid < 12) sm[BO2_F + tid] = bo2[tid];
        }
    }
    {   // x0 into A x-half (tf32), zero s-half
        int r = tid >> 2, c0 = (tid & 3) * 16;
        const float4* xs = (const float4*)(g_buf + ((size_t)row0 + r) * 64 + c0);
#pragma unroll
        for (int j = 0; j < 4; j++) {
            float4 v = xs[j];
            ((uint4*)(sm + A_F + r * 132 + c0))[j] =
                make_uint4(tf32r(v.x), tf32r(v.y), tf32r(v.z), tf32r(v.w));
            ((uint4*)(sm + A_F + r * 132 + 64 + c0))[j] = make_uint4(0, 0, 0, 0);
        }
    }

    float S[2][4][4];
#pragma unroll
    for (int a = 0; a < 2; a++)
#pragma unroll
        for (int b = 0; b < 4; b++)
#pragma unroll
            for (int c = 0; c < 4; c++) S[a][b][c] = 0.f;

    int prow = (tid >> 1) & 127, phalf = tid & 1;   // x-prefetch map (warps 0..7)

    for (int t = 0; t < CK_P; t++) {
        __syncthreads();   // A = [x_t | s_t] ready
        // ---- gate GEMM: C[32x32 tile] ----
        float C[2][4][4];
#pragma unroll
        for (int a = 0; a < 2; a++)
#pragma unroll
            for (int b = 0; b < 4; b++)
#pragma unroll
                for (int c = 0; c < 4; c++) C[a][b][c] = 0.f;
        {
            const uint32_t* Au = (const uint32_t*)(sm + A_F);
            const uint32_t* Bu = (const uint32_t*)(sm + WG_F);
            int ar0 = gr * 32 + g4, bn0 = gc * 32 + g4;
#pragma unroll
            for (int ks = 0; ks < 16; ks++) {
                int k0 = ks * 8 + t4;
                uint32_t b[4][2];
#pragma unroll
                for (int ni = 0; ni < 4; ni++) {
                    const uint32_t* bp = Bu + (bn0 + ni * 8) * 132 + k0;
                    b[ni][0] = bp[0]; b[ni][1] = bp[4];
                }
#pragma unroll
                for (int mi = 0; mi < 2; mi++) {
                    const uint32_t* ap = Au + (ar0 + mi * 16) * 132 + k0;
                    uint32_t a[4] = { ap[0], ap[8 * 132], ap[4], ap[8 * 132 + 4] };
#pragma unroll
                    for (int ni = 0; ni < 4; ni++) mma8(C[mi][ni], a, b[ni]);
                }
            }
        }
        __syncthreads();   // gate done; A s-half free to overwrite
        if (wid < 8) {     // r-half: rs = sigm(C+bg)*s  -> A s-half (tf32)
#pragma unroll
            for (int mi = 0; mi < 2; mi++)
#pragma unroll
                for (int ni = 0; ni < 4; ni++) {
                    int colb = gc * 32 + ni * 8 + 2 * t4;
                    float b0 = sm[BG_F + colb], b1 = sm[BG_F + colb + 1];
#pragma unroll
                    for (int e = 0; e < 2; e++) {
                        int r = gr * 32 + mi * 16 + g4 + e * 8;
                        float2* sp = (float2*)(sm + A_F + r * 132 + 64 + colb);
                        float2 sv = *sp;
                        float r0 = sigm(C[mi][ni][e * 2 + 0] + b0) * sv.x;
                        float r1 = sigm(C[mi][ni][e * 2 + 1] + b1) * sv.y;
                        *(uint2*)sp = make_uint2(tf32r(r0), tf32r(r1));
                    }
                }
        } else {           // u-half: u = sigm(C+bg), keep in regs (overwrite C)
#pragma unroll
            for (int mi = 0; mi < 2; mi++)
#pragma unroll
                for (int ni = 0; ni < 4; ni++) {
                    int colb = gc * 32 + ni * 8 + 2 * t4;
                    float b0 = sm[BG_F + colb], b1 = sm[BG_F + colb + 1];
                    C[mi][ni][0] = sigm(C[mi][ni][0] + b0);
                    C[mi][ni][1] = sigm(C[mi][ni][1] + b1);
                    C[mi][ni][2] = sigm(C[mi][ni][2] + b0);
                    C[mi][ni][3] = sigm(C[mi][ni][3] + b1);
                }
        }
        __syncthreads();   // rs visible
        // ---- cand GEMM (warps 8..15) || x_{t+1} prefetch (warps 0..7) ----
        float C2[2][4][4];
        float4 xf[8];
        if (wid >= 8) {
#pragma unroll
            for (int a = 0; a < 2; a++)
#pragma unroll
                for (int b = 0; b < 4; b++)
#pragma unroll
                    for (int c = 0; c < 4; c++) C2[a][b][c] = 0.f;
            const uint32_t* Au = (const uint32_t*)(sm + A_F);
            const uint32_t* Bu = (const uint32_t*)(sm + WC_F);
            int ar0 = gr * 32 + g4, bn0 = (gc - 2) * 32 + g4;
#pragma unroll
            for (int ks = 0; ks < 16; ks++) {
                int k0 = ks * 8 + t4;
                uint32_t b[4][2];
#pragma unroll
                for (int ni = 0; ni < 4; ni++) {
                    const uint32_t* bp = Bu + (bn0 + ni * 8) * 132 + k0;
                    b[ni][0] = bp[0]; b[ni][1] = bp[4];
                }
#pragma unroll
                for (int mi = 0; mi < 2; mi++) {
                    const uint32_t* ap = Au + (ar0 + mi * 16) * 132 + k0;
                    uint32_t a[4] = { ap[0], ap[8 * 132], ap[4], ap[8 * 132 + 4] };
#pragma unroll
                    for (int ni = 0; ni < 4; ni++) mma8(C2[mi][ni], a, b[ni]);
                }
            }
        } else if (t + 1 < CK_P) {
            const float4* src = (const float4*)(g_buf +
                ((size_t)(t + 1) * CK_BN + row0 + prow) * 64 + phalf * 32);
#pragma unroll
            for (int j = 0; j < 8; j++) xf[j] = src[j];
        }
        __syncthreads();   // cand reads of A done
        if (wid >= 8) {    // state update: s = c + u*(s-c); refresh A s-half
            int cc = gc - 2;
#pragma unroll
            for (int mi = 0; mi < 2; mi++)
#pragma unroll
                for (int ni = 0; ni < 4; ni++) {
                    int ccol = cc * 32 + ni * 8 + 2 * t4;
                    float b0 = sm[BC_F + ccol], b1 = sm[BC_F + ccol + 1];
#pragma unroll
                    for (int e = 0; e < 2; e++) {
                        int r = gr * 32 + mi * 16 + g4 + e * 8;
                        float c0 = tanh_f(C2[mi][ni][e * 2 + 0] + b0);
                        float c1 = tanh_f(C2[mi][ni][e * 2 + 1] + b1);
                        float s0 = S[mi][ni][e * 2 + 0], s1 = S[mi][ni][e * 2 + 1];
                        float u0 = C[mi][ni][e * 2 + 0], u1 = C[mi][ni][e * 2 + 1];
                        float n0 = fmaf(u0, s0 - c0, c0);
                        float n1 = fmaf(u1, s1 - c1, c1);
                        S[mi][ni][e * 2 + 0] = n0; S[mi][ni][e * 2 + 1] = n1;
                        *(uint2*)(sm + A_F + r * 132 + 64 + ccol) =
                            make_uint2(tf32r(n0), tf32r(n1));
                        if (!FINAL)
                            *(float2*)(g_buf + ((size_t)t * CK_BN + row0 + r) * 64 + ccol) =
                                make_float2(n0, n1);
                    }
                }
        } else if (t + 1 < CK_P) {   // write x_{t+1} into A x-half
#pragma unroll
            for (int j = 0; j < 8; j++) {
                ((uint4*)(sm + A_F + prow * 132 + phalf * 32))[j] =
                    make_uint4(tf32r(xf[j].x), tf32r(xf[j].y),
                               tf32r(xf[j].z), tf32r(xf[j].w));
            }
        }
    }

    if (FINAL) {
        __syncthreads();
        if (wid >= 8) {    // h -> k-major buffer (reuse sWg region)
            int cc = gc - 2;
#pragma unroll
            for (int mi = 0; mi < 2; mi++)
#pragma unroll
                for (int ni = 0; ni < 4; ni++) {
                    int ccol = cc * 32 + ni * 8 + 2 * t4;
#pragma unroll
                    for (int e = 0; e < 2; e++) {
                        int r = gr * 32 + mi * 16 + g4 + e * 8;
                        sm[WG_F + ccol * 132 + r]       = S[mi][ni][e * 2 + 0];
                        sm[WG_F + (ccol + 1) * 132 + r] = S[mi][ni][e * 2 + 1];
                    }
                }
        }
        __syncthreads();
        // o1 = relu(h @ Wo1 + bo1)
        int r2 = tid & 127, f0 = (tid >> 7) * 16;
        float a1[16];
#pragma unroll
        for (int j = 0; j < 16; j++) a1[j] = sm[BO1_F + f0 + j];
        for (int k = 0; k < 64; k++) {
            float hv = sm[WG_F + k * 132 + r2];
            const float4* wr = (const float4*)(sm + WO1_F + k * 64 + f0);
#pragma unroll
            for (int q = 0; q < 4; q++) {
                float4 w = wr[q];
                a1[q*4+0] = fmaf(hv, w.x, a1[q*4+0]);
                a1[q*4+1] = fmaf(hv, w.y, a1[q*4+1]);
                a1[q*4+2] = fmaf(hv, w.z, a1[q*4+2]);
                a1[q*4+3] = fmaf(hv, w.w, a1[q*4+3]);
            }
        }
        __syncthreads();
#pragma unroll
        for (int j = 0; j < 16; j++)
            sm[WC_F + (f0 + j) * 132 + r2] = fmaxf(a1[j], 0.f);
        __syncthreads();
        // y = o1 @ Wo2 + bo2 -> out[b][q][n]
        for (int idx = tid; idx < 128 * 12; idx += 512) {
            int row = idx / 12, q = idx - row * 12;
            float a = sm[BO2_F + q];
#pragma unroll 16
            for (int k = 0; k < 64; k++)
                a = fmaf(sm[WC_F + k * 132 + row], sm[WO2_F + k * 12 + q], a);
            int rg = row0 + row;
            int b = rg >> 10, n = rg & 1023;
            out[((size_t)b * CK_Q + q) * CK_N + n] = a;
        }
    }
}

// ---------------------------------------------------------------- launch
extern "C" void kernel_launch(void* const* d_in, const int* in_sizes, int n_in,
                              void* d_out, int out_size) {
    const float* X     = (const float*)d_in[0];
    const float* SE    = (const float*)d_in[3];
    const float* W_se1 = (const float*)d_in[4];
    const float* b_se1 = (const float*)d_in[5];
    const float* W_se2 = (const float*)d_in[6];
    const float* b_se2 = (const float*)d_in[7];
    const float* W_te1 = (const float*)d_in[8];
    const float* b_te1 = (const float*)d_in[9];
    const float* W_te2 = (const float*)d_in[10];
    const float* b_te2 = (const float*)d_in[11];
    const float* W_in1 = (const float*)d_in[12];
    const float* b_in1 = (const float*)d_in[13];
    const float* W_in2 = (const float*)d_in[14];
    const float* b_in2 = (const float*)d_in[15];
    const float* Wg1   = (const float*)d_in[16];
    const float* bg1   = (const float*)d_in[17];
    const float* Wc1   = (const float*)d_in[18];
    const float* bc1   = (const float*)d_in[19];
    const float* Wg2   = (const float*)d_in[20];
    const float* bg2   = (const float*)d_in[21];
    const float* Wc2   = (const float*)d_in[22];
    const float* bc2   = (const float*)d_in[23];
    const float* W_o1  = (const float*)d_in[24];
    const float* b_o1  = (const float*)d_in[25];
    const float* W_o2  = (const float*)d_in[26];
    const float* b_o2  = (const float*)d_in[27];
    const int*   TE    = (const int*)d_in[28];
    float* out = (float*)d_out;

    size_t smem = (size_t)SMEM_F * sizeof(float);
    cudaFuncSetAttribute(gru3_k<0, false>, cudaFuncAttributeMaxDynamicSharedMemorySize, (int)smem);
    cudaFuncSetAttribute(gru3_k<1, true>,  cudaFuncAttributeMaxDynamicSharedMemorySize, (int)smem);

    fold3_k<<<66, 256>>>(Wg1, Wc1, Wg2, Wc2);
    se_k<<<CK_N, 64>>>(SE, W_se1, b_se1, W_se2, b_se2);
    te_k<<<CK_B * CK_P, 64>>>(TE, W_te1, b_te1, W_te2, b_te2);
    xe_k<<<(CK_P * CK_BN) / 256, 256>>>(X, W_in1, b_in1, W_in2, b_in2);
    gru3_k<0, false><<<CK_BN / 128, 512, smem>>>(bg1, bc1, nullptr, nullptr, nullptr, nullptr, nullptr);
    gru3_k<1, true><<<CK_BN / 128, 512, smem>>>(bg2, bc2, W_o1, b_o1, W_o2, b_o2, out);
}

// round 13
// speedup vs baseline: 5.3525x; 1.2618x over previous
#include <cuda_runtime.h>
#include <cstdint>

#define CK_B 64
#define CK_P 12
#define CK_Q 12
#define CK_N 1024
#define CK_D 64
#define CK_BN (CK_B*CK_N)

__device__ float g_buf[(size_t)CK_P * CK_BN * CK_D];
__device__ float g_se2[CK_N * CK_D];
__device__ float g_te2[CK_B * CK_P * CK_D];
// Folded (support==I), transposed [n][k] with k-stride 132, tf32-rounded
__device__ float g_WgT1[128 * 132];
__device__ float g_WgT2[128 * 132];
__device__ float g_WcT1[64 * 132];
__device__ float g_WcT2[64 * 132];
__device__ float g_W2T[64 * 68];   // W_in2 transposed [n][k], stride 68, tf32

__device__ __forceinline__ float sigm(float x) {
    return __fdividef(1.0f, 1.0f + __expf(-x));
}
__device__ __forceinline__ float tanh_f(float x) {
    return __fdividef(2.0f, 1.0f + __expf(-2.0f * x)) - 1.0f;
}
__device__ __forceinline__ uint32_t tf32r(float x) {
    uint32_t r; asm("cvt.rna.tf32.f32 %0, %1;" : "=r"(r) : "f"(x)); return r;
}
// m16n8k8 tf32 mma, C += A*B
__device__ __forceinline__ void mma8(float* c, const uint32_t* a, const uint32_t* b) {
    asm volatile(
        "mma.sync.aligned.m16n8k8.row.col.f32.tf32.tf32.f32 "
        "{%0,%1,%2,%3}, {%4,%5,%6,%7}, {%8,%9}, {%0,%1,%2,%3};"
        : "+f"(c[0]), "+f"(c[1]), "+f"(c[2]), "+f"(c[3])
        : "r"(a[0]), "r"(a[1]), "r"(a[2]), "r"(a[3]), "r"(b[0]), "r"(b[1]));
}

// gru SMEM float-index layout (223296 B)
#define WG_F   0
#define WC_F   16896
#define A_F    25344
#define U_F    42240     // [128][66]
#define BG_F   50688
#define BC_F   50816
#define WO1_F  50880
#define WO2_F  54976
#define BO1_F  55744
#define BO2_F  55808
#define SMEM_F 55824

// ---------------------------------------------------------------- weight prep
__global__ void fold3_k(const float* __restrict__ Wg1, const float* __restrict__ Wc1,
                        const float* __restrict__ Wg2, const float* __restrict__ Wc2,
                        const float* __restrict__ W2) {
    int i = blockIdx.x * 256 + threadIdx.x;
    if (i < 128 * 132) {
        int n = i / 132, k = i - n * 132;
        float v1 = 0.f, v2 = 0.f;
        if (k < 128) {
            v1 = __uint_as_float(tf32r(Wg1[k * 128 + n] + Wg1[(k + 128) * 128 + n]));
            v2 = __uint_as_float(tf32r(Wg2[k * 128 + n] + Wg2[(k + 128) * 128 + n]));
        }
        g_WgT1[i] = v1; g_WgT2[i] = v2;
    }
    if (i < 64 * 132) {
        int n = i / 132, k = i - n * 132;
        float v1 = 0.f, v2 = 0.f;
        if (k < 128) {
            v1 = __uint_as_float(tf32r(Wc1[k * 64 + n] + Wc1[(k + 128) * 64 + n]));
            v2 = __uint_as_float(tf32r(Wc2[k * 64 + n] + Wc2[(k + 128) * 64 + n]));
        }
        g_WcT1[i] = v1; g_WcT2[i] = v2;
    }
    if (i < 64 * 68) {
        int n = i / 68, k = i - n * 68;
        g_W2T[i] = (k < 64) ? __uint_as_float(tf32r(W2[k * 64 + n])) : 0.f;
    }
}

// ---------------------------------------------------------------- SE embedding
__global__ void se_k(const float* __restrict__ SE, const float* __restrict__ W1,
                     const float* __restrict__ b1, const float* __restrict__ W2,
                     const float* __restrict__ b2) {
    __shared__ float srow[64];
    __shared__ float h[64];
    int n = blockIdx.x, d = threadIdx.x;
    srow[d] = SE[n * 64 + d];
    __syncthreads();
    float a = b1[d];
#pragma unroll 16
    for (int k = 0; k < 64; k++) a = fmaf(srow[k], W1[k * 64 + d], a);
    h[d] = fmaxf(a, 0.f);
    __syncthreads();
    float o = b2[d];
#pragma unroll 16
    for (int k = 0; k < 64; k++) o = fmaf(h[k], W2[k * 64 + d], o);
    g_se2[n * 64 + d] = o;
}

// ---------------------------------------------------------------- TE embedding
__global__ void te_k(const int* __restrict__ TE, const float* __restrict__ W1,
                     const float* __restrict__ b1, const float* __restrict__ W2,
                     const float* __restrict__ b2) {
    __shared__ float h[64];
    int bp = blockIdx.x;
    int b = bp / 12, p = bp % 12, d = threadIdx.x;
    int dow = TE[(b * 24 + p) * 2 + 0];
    int tod = TE[(b * 24 + p) * 2 + 1];
    float a = W1[dow * 64 + d] + W1[(7 + tod) * 64 + d] + b1[d];
    h[d] = fmaxf(a, 0.f);
    __syncthreads();
    float o = b2[d];
#pragma unroll 16
    for (int k = 0; k < 64; k++) o = fmaf(h[k], W2[k * 64 + d], o);
    g_te2[bp * 64 + d] = o;
}

// ---------------------------------------------------------------- FC_X_in + STE (tensor core)
// Block = 128 consecutive positions (same t,b). h = relu(x*w1+b1) staged tf32,
// then [128x64] @ W2T[64x64] via m16n8k8; epilogue adds b2+te (uniform) + se.
#define XSB_F 0          // W2T [64][68]
#define XSH_F 4352       // h   [128][68]
#define XBT_F 13056      // b2+te [64]
#define XW1_F 13120      // w1 [64]
#define XB1_F 13184      // b1 [64]
#define XSM_F 13248
__global__ void __launch_bounds__(256) xe2_k(
        const float* __restrict__ X, const float* __restrict__ W1,
        const float* __restrict__ b1, const float* __restrict__ b2) {
    extern __shared__ float xs[];
    int tid = threadIdx.x, wid = tid >> 5, lane = tid & 31;
    int g4 = lane >> 2, t4 = lane & 3;
    int gr = wid & 3, gc = wid >> 2;   // 8 warps: 4 row groups x 2 col groups

    size_t pbase = (size_t)blockIdx.x * 128;
    int t = (int)(pbase >> 16);
    int r16 = (int)(pbase & 65535);
    int b = r16 >> 10, n0 = r16 & 1023;

    for (int i = tid; i < 64 * 68; i += 256) xs[XSB_F + i] = g_W2T[i];
    if (tid < 64) {
        xs[XBT_F + tid] = b2[tid] + g_te2[(b * CK_P + t) * 64 + tid];
        xs[XW1_F + tid] = W1[tid];
        xs[XB1_F + tid] = b1[tid];
    }
    __syncthreads();

    {   // h: thread -> row tid>>1, 32 d-values
        int r = tid >> 1, d0 = (tid & 1) * 32;
        float x = X[(b * CK_P + t) * CK_N + n0 + r];
        uint32_t* hp = (uint32_t*)(xs + XSH_F + r * 68 + d0);
#pragma unroll 8
        for (int d = 0; d < 32; d++)
            hp[d] = tf32r(fmaxf(fmaf(x, xs[XW1_F + d0 + d], xs[XB1_F + d0 + d]), 0.f));
    }
    __syncthreads();

    float C[2][4][4];
#pragma unroll
    for (int a = 0; a < 2; a++)
#pragma unroll
        for (int bq = 0; bq < 4; bq++)
#pragma unroll
            for (int c = 0; c < 4; c++) C[a][bq][c] = 0.f;
    {
        const uint32_t* Au = (const uint32_t*)(xs + XSH_F);
        const uint32_t* Bu = (const uint32_t*)(xs + XSB_F);
        int ar0 = gr * 32 + g4, bn0 = gc * 32 + g4;
#pragma unroll
        for (int ks = 0; ks < 8; ks++) {
            int k0 = ks * 8 + t4;
            uint32_t bb[4][2];
#pragma unroll
            for (int ni = 0; ni < 4; ni++) {
                const uint32_t* bp = Bu + (bn0 + ni * 8) * 68 + k0;
                bb[ni][0] = bp[0]; bb[ni][1] = bp[4];
            }
#pragma unroll
            for (int mi = 0; mi < 2; mi++) {
                const uint32_t* ap = Au + (ar0 + mi * 16) * 68 + k0;
                uint32_t a[4] = { ap[0], ap[8 * 68], ap[4], ap[8 * 68 + 4] };
#pragma unroll
                for (int ni = 0; ni < 4; ni++) mma8(C[mi][ni], a, bb[ni]);
            }
        }
    }
#pragma unroll
    for (int mi = 0; mi < 2; mi++)
#pragma unroll
        for (int ni = 0; ni < 4; ni++) {
            int col = gc * 32 + ni * 8 + 2 * t4;
            float bt0 = xs[XBT_F + col], bt1 = xs[XBT_F + col + 1];
#pragma unroll
            for (int e = 0; e < 2; e++) {
                int r = gr * 32 + mi * 16 + g4 + e * 8;
                float2 se = *(const float2*)(g_se2 + (n0 + r) * 64 + col);
                float2 o;
                o.x = C[mi][ni][e * 2 + 0] + bt0 + se.x;
                o.y = C[mi][ni][e * 2 + 1] + bt1 + se.y;
                *(float2*)(g_buf + (pbase + r) * 64 + col) = o;
            }
        }
}

// ---------------------------------------------------------------- DCGRU (mma.sync tf32)
// Block = 128 rows x 12 steps. A[128][132] = [x | s] tf32 in SMEM.
// Gate: 16 warps, 32x32 tiles. u -> SMEM U buffer. Cand: ALL 16 warps, 32x16
// tiles; state S lives in cand-map registers. x_{t+1} LDG issued at top of step.
template<int LAYER, bool FINAL>
__global__ void __launch_bounds__(512, 1) gru3_k(
        const float* __restrict__ bg, const float* __restrict__ bc,
        const float* __restrict__ Wo1, const float* __restrict__ bo1,
        const float* __restrict__ Wo2, const float* __restrict__ bo2,
        float* __restrict__ out) {
    extern __shared__ float sm[];
    int tid = threadIdx.x, wid = tid >> 5, lane = tid & 31;
    int g4 = lane >> 2, t4 = lane & 3;
    int gr = wid & 3, gc = wid >> 2;   // gate tile; cand col group = gc (x16)
    int row0 = blockIdx.x * 128;

    {   // stage weights / biases
        const float* Wgs = (LAYER == 0) ? g_WgT1 : g_WgT2;
        for (int i = tid; i < 128 * 132; i += 512) sm[WG_F + i] = Wgs[i];
        const float* Wcs = (LAYER == 0) ? g_WcT1 : g_WcT2;
        for (int i = tid; i < 64 * 132; i += 512) sm[WC_F + i] = Wcs[i];
        if (tid < 128) sm[BG_F + tid] = bg[tid];
        if (tid < 64)  sm[BC_F + tid] = bc[tid];
        if (FINAL) {
            for (int i = tid; i < 4096; i += 512) sm[WO1_F + i] = Wo1[i];
            for (int i = tid; i < 768; i += 512)  sm[WO2_F + i] = Wo2[i];
            if (tid < 64) sm[BO1_F + tid] = bo1[tid];
            if (tid < 12) sm[BO2_F + tid] = bo2[tid];
        }
    }
    int pr = tid >> 2, pc = (tid & 3) * 16;
    {   // x0 into A x-half (tf32), zero s-half
        const float4* xsrc = (const float4*)(g_buf + ((size_t)row0 + pr) * 64 + pc);
#pragma unroll
        for (int j = 0; j < 4; j++) {
            float4 v = xsrc[j];
            ((uint4*)(sm + A_F + pr * 132 + pc))[j] =
                make_uint4(tf32r(v.x), tf32r(v.y), tf32r(v.z), tf32r(v.w));
            ((uint4*)(sm + A_F + pr * 132 + 64 + pc))[j] = make_uint4(0, 0, 0, 0);
        }
    }

    float S[2][2][4];
#pragma unroll
    for (int a = 0; a < 2; a++)
#pragma unroll
        for (int b = 0; b < 2; b++)
#pragma unroll
            for (int c = 0; c < 4; c++) S[a][b][c] = 0.f;

    for (int t = 0; t < CK_P; t++) {
        __syncthreads();   // A = [x_t | s_t] ready
        // issue x_{t+1} prefetch (overlaps gate MMA)
        float4 xf[4];
        if (t + 1 < CK_P) {
            const float4* src = (const float4*)(g_buf +
                ((size_t)(t + 1) * CK_BN + row0 + pr) * 64 + pc);
#pragma unroll
            for (int j = 0; j < 4; j++) xf[j] = src[j];
        }
        // ---- gate GEMM: 32x32 tiles ----
        float C[2][4][4];
#pragma unroll
        for (int a = 0; a < 2; a++)
#pragma unroll
            for (int b = 0; b < 4; b++)
#pragma unroll
                for (int c = 0; c < 4; c++) C[a][b][c] = 0.f;
        {
            const uint32_t* Au = (const uint32_t*)(sm + A_F);
            const uint32_t* Bu = (const uint32_t*)(sm + WG_F);
            int ar0 = gr * 32 + g4, bn0 = gc * 32 + g4;
#pragma unroll
            for (int ks = 0; ks < 16; ks++) {
                int k0 = ks * 8 + t4;
                uint32_t b[4][2];
#pragma unroll
                for (int ni = 0; ni < 4; ni++) {
                    const uint32_t* bp = Bu + (bn0 + ni * 8) * 132 + k0;
                    b[ni][0] = bp[0]; b[ni][1] = bp[4];
                }
#pragma unroll
                for (int mi = 0; mi < 2; mi++) {
                    const uint32_t* ap = Au + (ar0 + mi * 16) * 132 + k0;
                    uint32_t a[4] = { ap[0], ap[8 * 132], ap[4], ap[8 * 132 + 4] };
#pragma unroll
                    for (int ni = 0; ni < 4; ni++) mma8(C[mi][ni], a, b[ni]);
                }
            }
        }
        __syncthreads();   // gate done; A s-half stable for epilogue reads
        if (wid < 8) {     // r-half: rs = sigm(C+bg)*s -> A s-half (tf32)
#pragma unroll
            for (int mi = 0; mi < 2; mi++)
#pragma unroll
                for (int ni = 0; ni < 4; ni++) {
                    int colb = gc * 32 + ni * 8 + 2 * t4;
                    float b0 = sm[BG_F + colb], b1 = sm[BG_F + colb + 1];
#pragma unroll
                    for (int e = 0; e < 2; e++) {
                        int r = gr * 32 + mi * 16 + g4 + e * 8;
                        float2* sp = (float2*)(sm + A_F + r * 132 + 64 + colb);
                        float2 sv = *sp;
                        float r0 = sigm(C[mi][ni][e * 2 + 0] + b0) * sv.x;
                        float r1 = sigm(C[mi][ni][e * 2 + 1] + b1) * sv.y;
                        *(uint2*)sp = make_uint2(tf32r(r0), tf32r(r1));
                    }
                }
        } else {           // u-half -> U buffer
#pragma unroll
            for (int mi = 0; mi < 2; mi++)
#pragma unroll
                for (int ni = 0; ni < 4; ni++) {
                    int colb = gc * 32 + ni * 8 + 2 * t4;   // 64..127
                    int ucol = colb - 64;
                    float b0 = sm[BG_F + colb], b1 = sm[BG_F + colb + 1];
#pragma unroll
                    for (int e = 0; e < 2; e++) {
                        int r = gr * 32 + mi * 16 + g4 + e * 8;
                        float u0 = sigm(C[mi][ni][e * 2 + 0] + b0);
                        float u1 = sigm(C[mi][ni][e * 2 + 1] + b1);
                        *(float2*)(sm + U_F + r * 66 + ucol) = make_float2(u0, u1);
                    }
                }
        }
        __syncthreads();   // rs + U visible
        // ---- cand GEMM: ALL 16 warps, 32x16 tiles ----
        float C2[2][2][4];
#pragma unroll
        for (int a = 0; a < 2; a++)
#pragma unroll
            for (int b = 0; b < 2; b++)
#pragma unroll
                for (int c = 0; c < 4; c++) C2[a][b][c] = 0.f;
        {
            const uint32_t* Au = (const uint32_t*)(sm + A_F);
            const uint32_t* Bu = (const uint32_t*)(sm + WC_F);
            int ar0 = gr * 32 + g4, bn0 = gc * 16 + g4;
#pragma unroll
            for (int ks = 0; ks < 16; ks++) {
                int k0 = ks * 8 + t4;
                uint32_t b[2][2];
#pragma unroll
                for (int ni = 0; ni < 2; ni++) {
                    const uint32_t* bp = Bu + (bn0 + ni * 8) * 132 + k0;
                    b[ni][0] = bp[0]; b[ni][1] = bp[4];
                }
#pragma unroll
                for (int mi = 0; mi < 2; mi++) {
                    const uint32_t* ap = Au + (ar0 + mi * 16) * 132 + k0;
                    uint32_t a[4] = { ap[0], ap[8 * 132], ap[4], ap[8 * 132 + 4] };
#pragma unroll
                    for (int ni = 0; ni < 2; ni++) mma8(C2[mi][ni], a, b[ni]);
                }
            }
        }
        __syncthreads();   // cand reads of A done
        // ---- update (all warps own their cand tile) ----
#pragma unroll
        for (int mi = 0; mi < 2; mi++)
#pragma unroll
            for (int ni = 0; ni < 2; ni++) {
                int ccol = gc * 16 + ni * 8 + 2 * t4;
                float cb0 = sm[BC_F + ccol], cb1 = sm[BC_F + ccol + 1];
#pragma unroll
                for (int e = 0; e < 2; e++) {
                    int r = gr * 32 + mi * 16 + g4 + e * 8;
                    float2 uu = *(const float2*)(sm + U_F + r * 66 + ccol);
                    float c0 = tanh_f(C2[mi][ni][e * 2 + 0] + cb0);
                    float c1 = tanh_f(C2[mi][ni][e * 2 + 1] + cb1);
                    float s0 = S[mi][ni][e * 2 + 0], s1 = S[mi][ni][e * 2 + 1];
                    float n0 = fmaf(uu.x, s0 - c0, c0);
                    float n1 = fmaf(uu.y, s1 - c1, c1);
                    S[mi][ni][e * 2 + 0] = n0; S[mi][ni][e * 2 + 1] = n1;
                    *(uint2*)(sm + A_F + r * 132 + 64 + ccol) =
                        make_uint2(tf32r(n0), tf32r(n1));
                    if (!FINAL)
                        *(float2*)(g_buf + ((size_t)t * CK_BN + row0 + r) * 64 + ccol) =
                            make_float2(n0, n1);
                }
            }
        if (t + 1 < CK_P) {   // write prefetched x into A x-half
#pragma unroll
            for (int j = 0; j < 4; j++)
                ((uint4*)(sm + A_F + pr * 132 + pc))[j] =
                    make_uint4(tf32r(xf[j].x), tf32r(xf[j].y),
                               tf32r(xf[j].z), tf32r(xf[j].w));
        }
    }

    if (FINAL) {
        __syncthreads();
        {   // h -> k-major buffer (reuse WG region); all warps, cand map
#pragma unroll
            for (int mi = 0; mi < 2; mi++)
#pragma unroll
                for (int ni = 0; ni < 2; ni++) {
                    int ccol = gc * 16 + ni * 8 + 2 * t4;
#pragma unroll
                    for (int e = 0; e < 2; e++) {
                        int r = gr * 32 + mi * 16 + g4 + e * 8;
                        sm[WG_F + ccol * 132 + r]       = S[mi][ni][e * 2 + 0];
                        sm[WG_F + (ccol + 1) * 132 + r] = S[mi][ni][e * 2 + 1];
                    }
                }
        }
        __syncthreads();
        // o1 = relu(h @ Wo1 + bo1)
        int r2 = tid & 127, f0 = (tid >> 7) * 16;
        float a1[16];
#pragma unroll
        for (int j = 0; j < 16; j++) a1[j] = sm[BO1_F + f0 + j];
        for (int k = 0; k < 64; k++) {
            float hv = sm[WG_F + k * 132 + r2];
            const float4* wr = (const float4*)(sm + WO1_F + k * 64 + f0);
#pragma unroll
            for (int q = 0; q < 4; q++) {
                float4 w = wr[q];
                a1[q*4+0] = fmaf(hv, w.x, a1[q*4+0]);
                a1[q*4+1] = fmaf(hv, w.y, a1[q*4+1]);
                a1[q*4+2] = fmaf(hv, w.z, a1[q*4+2]);
                a1[q*4+3] = fmaf(hv, w.w, a1[q*4+3]);
            }
        }
        __syncthreads();
#pragma unroll
        for (int j = 0; j < 16; j++)
            sm[WC_F + (f0 + j) * 132 + r2] = fmaxf(a1[j], 0.f);
        __syncthreads();
        // y = o1 @ Wo2 + bo2 -> out[b][q][n]
        for (int idx = tid; idx < 128 * 12; idx += 512) {
            int row = idx / 12, q = idx - row * 12;
            float a = sm[BO2_F + q];
#pragma unroll 16
            for (int k = 0; k < 64; k++)
                a = fmaf(sm[WC_F + k * 132 + row], sm[WO2_F + k * 12 + q], a);
            int rg = row0 + row;
            int b = rg >> 10, n = rg & 1023;
            out[((size_t)b * CK_Q + q) * CK_N + n] = a;
        }
    }
}

// ---------------------------------------------------------------- launch
extern "C" void kernel_launch(void* const* d_in, const int* in_sizes, int n_in,
                              void* d_out, int out_size) {
    const float* X     = (const float*)d_in[0];
    const float* SE    = (const float*)d_in[3];
    const float* W_se1 = (const float*)d_in[4];
    const float* b_se1 = (const float*)d_in[5];
    const float* W_se2 = (const float*)d_in[6];
    const float* b_se2 = (const float*)d_in[7];
    const float* W_te1 = (const float*)d_in[8];
    const float* b_te1 = (const float*)d_in[9];
    const float* W_te2 = (const float*)d_in[10];
    const float* b_te2 = (const float*)d_in[11];
    const float* W_in1 = (const float*)d_in[12];
    const float* b_in1 = (const float*)d_in[13];
    const float* W_in2 = (const float*)d_in[14];
    const float* b_in2 = (const float*)d_in[15];
    const float* Wg1   = (const float*)d_in[16];
    const float* bg1   = (const float*)d_in[17];
    const float* Wc1   = (const float*)d_in[18];
    const float* bc1   = (const float*)d_in[19];
    const float* Wg2   = (const float*)d_in[20];
    const float* bg2   = (const float*)d_in[21];
    const float* Wc2   = (const float*)d_in[22];
    const float* bc2   = (const float*)d_in[23];
    const float* W_o1  = (const float*)d_in[24];
    const float* b_o1  = (const float*)d_in[25];
    const float* W_o2  = (const float*)d_in[26];
    const float* b_o2  = (const float*)d_in[27];
    const int*   TE    = (const int*)d_in[28];
    float* out = (float*)d_out;

    size_t smem = (size_t)SMEM_F * sizeof(float);
    size_t xsm  = (size_t)XSM_F * sizeof(float);
    cudaFuncSetAttribute(gru3_k<0, false>, cudaFuncAttributeMaxDynamicSharedMemorySize, (int)smem);
    cudaFuncSetAttribute(gru3_k<1, true>,  cudaFuncAttributeMaxDynamicSharedMemorySize, (int)smem);
    cudaFuncSetAttribute(xe2_k, cudaFuncAttributeMaxDynamicSharedMemorySize, (int)xsm);

    fold3_k<<<66, 256>>>(Wg1, Wc1, Wg2, Wc2, W_in2);
    se_k<<<CK_N, 64>>>(SE, W_se1, b_se1, W_se2, b_se2);
    te_k<<<CK_B * CK_P, 64>>>(TE, W_te1, b_te1, W_te2, b_te2);
    xe2_k<<<(CK_P * CK_BN) / 128, 256, xsm>>>(X, W_in1, b_in1, b_in2);
    gru3_k<0, false><<<CK_BN / 128, 512, smem>>>(bg1, bc1, nullptr, nullptr, nullptr, nullptr, nullptr);
    gru3_k<1, true><<<CK_BN / 128, 512, smem>>>(bg2, bc2, W_o1, b_o1, W_o2, b_o2, out);
}